// round 14
// baseline (speedup 1.0000x reference)
#include <cuda_runtime.h>
#include <cuda_bf16.h>
#include <cuda_fp16.h>
#include <cstdint>

// Problem constants
#define B_    32
#define S_    256
#define D_    256
#define U_    256
#define L_    16
#define DEG_  16
#define N_    (B_ * S_)        // 8192
#define E_    (N_ * DEG_)      // 131072
#define KA    256              // fp16 x
#define KB    256              // fp16 w^T
#define NMAT  33               // 16 in + 16 out + 1 self

// GEMM tiling: persistent-A. CTA 128x128 output tile, loops over mats.
// A tile resident (64KB = 4 slabs x 16KB); B double-buffered 16KB chunks.
#define MTILE   128
#define NTILE   128
#define BK      64                         // fp16 per K-chunk (128B rows)
#define SLAB    (MTILE * 128)              // 16KB
#define SMEM_B_OFF (4 * SLAB)              // A: 4 slabs = 64KB
#define SMEM_TOTAL (SMEM_B_OFF + 2 * SLAB) // 96KB

// Fused prep block ranges
#define PREP_X_BLKS   N_          // 8192
#define PREP_W_BLKS   (64 * NMAT) // 2112
#define PREP_E_BLKS   (E_ / 256)  // 512
#define PREP_G_BLKS   (N_ / 8)    // 1024
#define PREP_TOTAL (PREP_X_BLKS + PREP_W_BLKS + PREP_E_BLKS + PREP_G_BLKS)

// ---------------------------------------------------------------------------
// Scratch (device globals: allocation-free rule)
// ---------------------------------------------------------------------------
__device__ __align__(16) __half g_xa[(size_t)N_ * KA];            // [N,256] fp16 x
__device__ __align__(16) __half g_wb[(size_t)NMAT * U_ * KB];     // [33][u][256] fp16 w^T
__device__ __align__(16) __half g_all_in [(size_t)L_ * N_ * U_];  // fp16 potentials
__device__ __align__(16) __half g_all_out[(size_t)L_ * N_ * U_];
__device__ __align__(16) __half g_same[(size_t)N_ * U_];
__device__ float g_gin[N_], g_gout[N_], g_gloop[N_];
__device__ int   g_ein[E_], g_lin[E_], g_eout[E_], g_lout[E_];

// ---------------------------------------------------------------------------
// PTX helpers (sm_80+-portable only)
// ---------------------------------------------------------------------------
__device__ __forceinline__ uint32_t smem_u32(const void* p) {
    uint32_t a;
    asm("{ .reg .u64 t; cvta.to.shared.u64 t, %1; cvt.u32.u64 %0, t; }" : "=r"(a) : "l"(p));
    return a;
}
__device__ __forceinline__ void cp_async16(uint32_t dst, const void* src) {
    asm volatile("cp.async.cg.shared.global [%0], [%1], 16;" :: "r"(dst), "l"(src) : "memory");
}
#define CP_COMMIT() asm volatile("cp.async.commit_group;" ::: "memory")

__device__ __forceinline__ uint32_t swz128(uint32_t off) {
    return off ^ ((off >> 3) & 0x70);
}
__device__ __forceinline__ void ldmatrix_x4(uint32_t* r, uint32_t addr) {
    asm volatile("ldmatrix.sync.aligned.m8n8.x4.shared.b16 {%0,%1,%2,%3}, [%4];"
                 : "=r"(r[0]), "=r"(r[1]), "=r"(r[2]), "=r"(r[3]) : "r"(addr));
}
__device__ __forceinline__ void ldmatrix_x2(uint32_t* r, uint32_t addr) {
    asm volatile("ldmatrix.sync.aligned.m8n8.x2.shared.b16 {%0,%1}, [%2];"
                 : "=r"(r[0]), "=r"(r[1]) : "r"(addr));
}
__device__ __forceinline__ void mma_f16(float* c, const uint32_t* a, const uint32_t* b) {
    asm volatile(
        "mma.sync.aligned.m16n8k16.row.col.f32.f16.f16.f32 "
        "{%0,%1,%2,%3}, {%4,%5,%6,%7}, {%8,%9}, {%0,%1,%2,%3};"
        : "+f"(c[0]), "+f"(c[1]), "+f"(c[2]), "+f"(c[3])
        : "r"(a[0]), "r"(a[1]), "r"(a[2]), "r"(a[3]), "r"(b[0]), "r"(b[1]));
}

// ---------------------------------------------------------------------------
// Fused prep: x-convert | w-transpose | edge-decode | gates, by block range
// ---------------------------------------------------------------------------
__device__ __forceinline__ int detect_is64(const int* p) {
    int z = 1;
    #pragma unroll
    for (int i = 1; i < 128; i += 2) z &= (p[i] == 0);
    return z;
}

__global__ void prep_fused_kernel(const float* __restrict__ src,
                                  const float* __restrict__ Vin,
                                  const float* __restrict__ Vout,
                                  const float* __restrict__ Ws,
                                  const void* __restrict__ arc_in,
                                  const void* __restrict__ lab_in,
                                  const void* __restrict__ arc_out,
                                  const void* __restrict__ lab_out,
                                  const float* __restrict__ vgin,
                                  const float* __restrict__ vgout,
                                  const float* __restrict__ wgloop) {
    const int blk = blockIdx.x;
    const int t = threadIdx.x;

    if (blk < PREP_X_BLKS) {
        // ---- x fp16 convert ----
        int n = blk;
        int s = n & (S_ - 1);
        int b = n >> 8;
        float x = src[(size_t)s * B_ * D_ + (size_t)b * D_ + t];
        g_xa[(size_t)n * KA + t] = __float2half(x);
        return;
    }
    if (blk < PREP_X_BLKS + PREP_W_BLKS) {
        // ---- w transpose to [u][d] fp16 ----
        int idx = blk - PREP_X_BLKS;
        int z = idx >> 6;             // /64
        int rem = idx & 63;
        int u0 = (rem & 7) * 32, d0 = (rem >> 3) * 32;
        const float* W;
        if (z < L_)          W = Vin  + (size_t)z * D_ * U_;
        else if (z < 2 * L_) W = Vout + (size_t)(z - L_) * D_ * U_;
        else                 W = Ws;
        __shared__ float tile[32][33];
        int tx = t & 31, ty = t >> 5;     // 32 x 8
        #pragma unroll
        for (int j = 0; j < 32; j += 8)
            tile[ty + j][tx] = W[(size_t)(d0 + ty + j) * U_ + u0 + tx];
        __syncthreads();
        __half* base = g_wb + (size_t)z * U_ * KB;
        #pragma unroll
        for (int j = 0; j < 32; j += 8) {
            int u = u0 + ty + j, d = d0 + tx;
            base[(size_t)u * KB + d] = __float2half(tile[tx][ty + j]);
        }
        return;
    }
    if (blk < PREP_X_BLKS + PREP_W_BLKS + PREP_E_BLKS) {
        // ---- edge decode ----
        __shared__ int s64;
        if (t == 0) s64 = detect_is64((const int*)arc_in);
        __syncthreads();
        int e = (blk - PREP_X_BLKS - PREP_W_BLKS) * 256 + t;
        int bi, si, li, bo, so, lo;
        if (s64) {
            const long long* ai = (const long long*)arc_in;
            const long long* ao = (const long long*)arc_out;
            bi = (int)ai[e];  si = (int)ai[E_ + e];  li = (int)((const long long*)lab_in)[e];
            bo = (int)ao[e];  so = (int)ao[E_ + e];  lo = (int)((const long long*)lab_out)[e];
        } else {
            const int* ai = (const int*)arc_in;
            const int* ao = (const int*)arc_out;
            bi = ai[e];  si = ai[E_ + e];  li = ((const int*)lab_in)[e];
            bo = ao[e];  so = ao[E_ + e];  lo = ((const int*)lab_out)[e];
        }
        g_ein[e]  = bi * S_ + si;  g_lin[e]  = li;
        g_eout[e] = bo * S_ + so;  g_lout[e] = lo;
        return;
    }
    // ---- gates (fp32, exact) ----
    {
        int base = blk - PREP_X_BLKS - PREP_W_BLKS - PREP_E_BLKS;
        int warp = base * 8 + (t >> 5);
        int lane = t & 31;
        int s = warp & (S_ - 1);
        int b = warp >> 8;
        const float* xr = src + (size_t)s * B_ * D_ + (size_t)b * D_;
        float a = 0.f, bb = 0.f, c = 0.f;
        #pragma unroll
        for (int d = lane; d < D_; d += 32) {
            float xv = xr[d];
            a  += xv * vgin[d];
            bb += xv * vgout[d];
            c  += xv * wgloop[d];
        }
        #pragma unroll
        for (int off = 16; off; off >>= 1) {
            a  += __shfl_xor_sync(0xffffffffu, a, off);
            bb += __shfl_xor_sync(0xffffffffu, bb, off);
            c  += __shfl_xor_sync(0xffffffffu, c, off);
        }
        if (lane == 0) { g_gin[warp] = a; g_gout[warp] = bb; g_gloop[warp] = c; }
    }
}

// ---------------------------------------------------------------------------
// Persistent-A GEMM: CTA owns (m0,n0); A resident; loops over mats, B streams.
// 8 warps (2m x 4n), warp tile 64x32, 2 CTAs/SM, single wave (256 CTAs).
// ---------------------------------------------------------------------------
__device__ __forceinline__ void load_b_chunk(uint32_t sbase, int buf, int mat,
                                             int kt, int n0, int t) {
    uint32_t bb = sbase + SMEM_B_OFF + buf * SLAB;
    const char* w0 = (const char*)(g_wb + (size_t)mat * U_ * KB + (size_t)n0 * KB);
    #pragma unroll
    for (int r = 0; r < 4; r++) {
        int i = r * 256 + t;                  // 1024 16B segments
        int row = i >> 3, seg = i & 7;
        const char* src = w0 + (((size_t)row * KB + (size_t)kt * BK) << 1) + seg * 16;
        cp_async16(bb + swz128(row * 128 + seg * 16), src);
    }
}

__global__ void __launch_bounds__(256, 2) gemm_mma_kernel() {
    extern __shared__ char smem[];
    uint32_t sbase = smem_u32(smem);
    const int t = threadIdx.x, wid = t >> 5, lane = t & 31;
    const int wm = wid & 1, wn = wid >> 1;            // 2m x 4n warp grid
    const int m0 = blockIdx.x * MTILE, n0 = blockIdx.y * NTILE;
    const int mat_lo  = blockIdx.z ? 16 : 0;
    const int nmats   = blockIdx.z ? 17 : 16;
    const int NC = nmats * 4;

    // Load A tile: 4 slabs (k-chunks), 128 rows x 128B each
    #pragma unroll
    for (int sl = 0; sl < 4; sl++) {
        uint32_t ab = sbase + sl * SLAB;
        #pragma unroll
        for (int r = 0; r < 4; r++) {
            int i = r * 256 + t;
            int row = i >> 3, seg = i & 7;
            const char* src = (const char*)g_xa +
                (((size_t)(m0 + row) * KA + (size_t)sl * BK) << 1) + seg * 16;
            cp_async16(ab + swz128(row * 128 + seg * 16), src);
        }
    }
    load_b_chunk(sbase, 0, mat_lo, 0, n0, t);
    CP_COMMIT();                               // group 0: A + B(0)

    float acc[4][4][4];
    #pragma unroll
    for (int i = 0; i < 4; i++)
        #pragma unroll
        for (int j = 0; j < 4; j++)
            #pragma unroll
            for (int q = 0; q < 4; q++) acc[i][j][q] = 0.f;

    const int a_row = wm * 64 + (lane & 15);
    const int a_cb  = (lane >> 4) * 16;
    const int b_row = wn * 32 + (lane & 7);
    const int b_cb  = ((lane >> 3) & 1) * 16;
    const int r0 = m0 + wm * 64 + (lane >> 2);
    const int c0 = n0 + wn * 32 + (lane & 3) * 2;

    for (int i = 0; i < NC; i++) {
        const int kt = i & 3;
        if (i + 1 < NC) {
            load_b_chunk(sbase, (i + 1) & 1, mat_lo + ((i + 1) >> 2), (i + 1) & 3, n0, t);
            CP_COMMIT();
            asm volatile("cp.async.wait_group 1;" ::: "memory");
        } else {
            asm volatile("cp.async.wait_group 0;" ::: "memory");
        }
        __syncthreads();

        uint32_t ab = sbase + kt * SLAB;
        uint32_t bb = sbase + SMEM_B_OFF + (i & 1) * SLAB;
        #pragma unroll
        for (int ks = 0; ks < 4; ks++) {
            const int kb = ks * 32;
            uint32_t a_frag[4][4], b_frag[4][2];
            #pragma unroll
            for (int mi = 0; mi < 4; mi++)
                ldmatrix_x4(a_frag[mi],
                    ab + swz128((a_row + mi * 16) * 128 + kb + a_cb));
            #pragma unroll
            for (int ni = 0; ni < 4; ni++)
                ldmatrix_x2(b_frag[ni],
                    bb + swz128((b_row + ni * 8) * 128 + kb + b_cb));
            #pragma unroll
            for (int mi = 0; mi < 4; mi++)
                #pragma unroll
                for (int ni = 0; ni < 4; ni++)
                    mma_f16(acc[mi][ni], a_frag[mi], b_frag[ni]);
        }
        __syncthreads();

        if (kt == 3) {
            const int mat = mat_lo + (i >> 2);
            __half* C;
            if (mat < L_)            C = g_all_in  + (size_t)mat * N_ * U_;
            else if (mat < 2 * L_)   C = g_all_out + (size_t)(mat - L_) * N_ * U_;
            else                     C = g_same;
            #pragma unroll
            for (int mi = 0; mi < 4; mi++) {
                #pragma unroll
                for (int ni = 0; ni < 4; ni++) {
                    __half* p0 = C + (size_t)(r0 + mi * 16) * U_ + c0 + ni * 8;
                    __half* p1 = p0 + 8 * U_;
                    *(__half2*)p0 = __floats2half2_rn(acc[mi][ni][0], acc[mi][ni][1]);
                    *(__half2*)p1 = __floats2half2_rn(acc[mi][ni][2], acc[mi][ni][3]);
                    #pragma unroll
                    for (int q = 0; q < 4; q++) acc[mi][ni][q] = 0.f;
                }
            }
        }
    }
}

// ---------------------------------------------------------------------------
// Gather + sigmoid-gated reduce + relu + sent_mask + transpose to [S,B,U]
// ---------------------------------------------------------------------------
__device__ __forceinline__ float sigmoidf_(float g) { return 1.f / (1.f + expf(-g)); }

__global__ void gather_kernel(const float* __restrict__ b_in,
                              const float* __restrict__ bg_in,
                              const float* __restrict__ b_out,
                              const float* __restrict__ bg_out,
                              const float* __restrict__ mask_in,
                              const float* __restrict__ mask_out,
                              const float* __restrict__ mask_loop,
                              const float* __restrict__ sent_mask,
                              float* __restrict__ out) {
    const int n = blockIdx.x;
    const int t = threadIdx.x;
    const int s = n & (S_ - 1);
    const int b = n >> 8;

    __shared__ float sp[33];
    __shared__ int   sidx[33];
    __shared__ int   sl[33];

    if (t < 33) {
        float p; int idx = 0, l = 0;
        if (t < 16) {
            int e = n * DEG_ + t;
            idx = g_ein[e]; l = g_lin[e];
            p = sigmoidf_(g_gin[idx] + bg_in[l]) * mask_in[(size_t)n * DEG_ + t];
        } else if (t < 32) {
            int k = t - 16;
            int e = n * DEG_ + k;
            idx = g_eout[e]; l = g_lout[e];
            p = sigmoidf_(g_gout[idx] + bg_out[l]) * mask_out[(size_t)n * DEG_ + k];
        } else {
            p = sigmoidf_(g_gloop[n]) * mask_loop[n];
        }
        sp[t] = p; sidx[t] = idx; sl[t] = l;
    }
    __syncthreads();

    const float sent = sent_mask[(size_t)s * B_ + b];
    float acc = sp[32] * __half2float(g_same[(size_t)n * U_ + t]);
    #pragma unroll
    for (int k = 0; k < 16; k++) {
        int l = sl[k];
        acc += sp[k] * (__half2float(g_all_in[((size_t)l * N_ + sidx[k]) * U_ + t])
                        + b_in[l * U_ + t]);
    }
    #pragma unroll
    for (int k = 16; k < 32; k++) {
        int l = sl[k];
        acc += sp[k] * (__half2float(g_all_out[((size_t)l * N_ + sidx[k]) * U_ + t])
                        + b_out[l * U_ + t]);
    }
    acc = fmaxf(acc, 0.f) * sent;
    out[(size_t)s * B_ * U_ + (size_t)b * U_ + t] = acc;
}

// ---------------------------------------------------------------------------
// Launch
// ---------------------------------------------------------------------------
extern "C" void kernel_launch(void* const* d_in, const int* in_sizes, int n_in,
                              void* d_out, int out_size) {
    const float* src        = (const float*)d_in[0];
    const float* V_in       = (const float*)d_in[1];
    const float* b_in       = (const float*)d_in[2];
    const float* V_in_gate  = (const float*)d_in[3];
    const float* b_in_gate  = (const float*)d_in[4];
    const float* V_out      = (const float*)d_in[5];
    const float* b_out      = (const float*)d_in[6];
    const float* V_out_gate = (const float*)d_in[7];
    const float* b_out_gate = (const float*)d_in[8];
    const float* W_self     = (const float*)d_in[9];
    const float* W_self_g   = (const float*)d_in[10];
    const void*  arc_in     = d_in[11];
    const void*  arc_out    = d_in[12];
    const void*  lab_in     = d_in[13];
    const void*  lab_out    = d_in[14];
    const float* mask_in    = (const float*)d_in[15];
    const float* mask_out   = (const float*)d_in[16];
    const float* mask_loop  = (const float*)d_in[17];
    const float* sent_mask  = (const float*)d_in[18];
    float* out = (float*)d_out;

    cudaFuncSetAttribute(gemm_mma_kernel,
                         cudaFuncAttributeMaxDynamicSharedMemorySize, SMEM_TOTAL);

    prep_fused_kernel<<<PREP_TOTAL, 256>>>(src, V_in, V_out, W_self,
                                           arc_in, lab_in, arc_out, lab_out,
                                           V_in_gate, V_out_gate, W_self_g);

    gemm_mma_kernel<<<dim3(N_ / MTILE, U_ / NTILE, 2), 256, SMEM_TOTAL>>>();

    gather_kernel<<<N_, U_>>>(b_in, b_in_gate, b_out, b_out_gate,
                              mask_in, mask_out, mask_loop, sent_mask, out);
}

// round 16
// speedup vs baseline: 1.0781x; 1.0781x over previous
#include <cuda_runtime.h>
#include <cuda_bf16.h>
#include <cuda_fp16.h>
#include <cstdint>

// Problem constants
#define B_    32
#define S_    256
#define D_    256
#define U_    256
#define L_    16
#define DEG_  16
#define N_    (B_ * S_)        // 8192
#define E_    (N_ * DEG_)      // 131072
#define KA    256              // fp16 x
#define KB    256              // fp16 w^T
#define NMAT  33               // 16 in + 16 out + 1 self

// GEMM tiling: CTA 128x128, 8 warps (2m x 4n), warp tile 64x32, occ 2
// (A,B) chunk pairs double-buffered -- the R12 configuration (best: 205.9us).
#define MTILE   128
#define NTILE   128
#define BK      64                         // fp16 per K-chunk (128B rows)
#define NCHUNK  (KA / BK)                  // 4
#define STAGE   (MTILE * 128 + NTILE * 128)    // 16KB A + 16KB B = 32768
#define SMEM_TOTAL (2 * STAGE)             // 65536

// Fused prep block ranges
#define PREP_X_BLKS   N_          // 8192
#define PREP_W_BLKS   (64 * NMAT) // 2112
#define PREP_E_BLKS   (E_ / 256)  // 512
#define PREP_G_BLKS   (N_ / 8)    // 1024
#define PREP_TOTAL (PREP_X_BLKS + PREP_W_BLKS + PREP_E_BLKS + PREP_G_BLKS)

// ---------------------------------------------------------------------------
// Scratch (device globals: allocation-free rule)
// ---------------------------------------------------------------------------
__device__ __align__(16) __half g_xa[(size_t)N_ * KA];            // [N,256] fp16 x
__device__ __align__(16) __half g_wb[(size_t)NMAT * U_ * KB];     // [33][u][256] fp16 w^T
__device__ __align__(16) __half g_all_in [(size_t)L_ * N_ * U_];  // fp16 potentials
__device__ __align__(16) __half g_all_out[(size_t)L_ * N_ * U_];
__device__ __align__(16) __half g_same[(size_t)N_ * U_];
__device__ float g_gin[N_], g_gout[N_], g_gloop[N_];
__device__ int   g_ein[E_], g_lin[E_], g_eout[E_], g_lout[E_];

// ---------------------------------------------------------------------------
// PTX helpers (sm_80+-portable only)
// ---------------------------------------------------------------------------
__device__ __forceinline__ uint32_t smem_u32(const void* p) {
    uint32_t a;
    asm("{ .reg .u64 t; cvta.to.shared.u64 t, %1; cvt.u32.u64 %0, t; }" : "=r"(a) : "l"(p));
    return a;
}
__device__ __forceinline__ void cp_async16(uint32_t dst, const void* src) {
    asm volatile("cp.async.cg.shared.global [%0], [%1], 16;" :: "r"(dst), "l"(src) : "memory");
}
#define CP_COMMIT() asm volatile("cp.async.commit_group;" ::: "memory")

__device__ __forceinline__ uint32_t swz128(uint32_t off) {
    return off ^ ((off >> 3) & 0x70);
}
__device__ __forceinline__ void ldmatrix_x4(uint32_t* r, uint32_t addr) {
    asm volatile("ldmatrix.sync.aligned.m8n8.x4.shared.b16 {%0,%1,%2,%3}, [%4];"
                 : "=r"(r[0]), "=r"(r[1]), "=r"(r[2]), "=r"(r[3]) : "r"(addr));
}
__device__ __forceinline__ void ldmatrix_x2(uint32_t* r, uint32_t addr) {
    asm volatile("ldmatrix.sync.aligned.m8n8.x2.shared.b16 {%0,%1}, [%2];"
                 : "=r"(r[0]), "=r"(r[1]) : "r"(addr));
}
__device__ __forceinline__ void mma_f16(float* c, const uint32_t* a, const uint32_t* b) {
    asm volatile(
        "mma.sync.aligned.m16n8k16.row.col.f32.f16.f16.f32 "
        "{%0,%1,%2,%3}, {%4,%5,%6,%7}, {%8,%9}, {%0,%1,%2,%3};"
        : "+f"(c[0]), "+f"(c[1]), "+f"(c[2]), "+f"(c[3])
        : "r"(a[0]), "r"(a[1]), "r"(a[2]), "r"(a[3]), "r"(b[0]), "r"(b[1]));
}

// ---------------------------------------------------------------------------
// Fused prep: x-convert | w-transpose | edge-decode | gates, by block range
// ---------------------------------------------------------------------------
__device__ __forceinline__ int detect_is64(const int* p) {
    int z = 1;
    #pragma unroll
    for (int i = 1; i < 128; i += 2) z &= (p[i] == 0);
    return z;
}

__global__ void prep_fused_kernel(const float* __restrict__ src,
                                  const float* __restrict__ Vin,
                                  const float* __restrict__ Vout,
                                  const float* __restrict__ Ws,
                                  const void* __restrict__ arc_in,
                                  const void* __restrict__ lab_in,
                                  const void* __restrict__ arc_out,
                                  const void* __restrict__ lab_out,
                                  const float* __restrict__ vgin,
                                  const float* __restrict__ vgout,
                                  const float* __restrict__ wgloop) {
    const int blk = blockIdx.x;
    const int t = threadIdx.x;

    if (blk < PREP_X_BLKS) {
        // ---- x fp16 convert ----
        int n = blk;
        int s = n & (S_ - 1);
        int b = n >> 8;
        float x = src[(size_t)s * B_ * D_ + (size_t)b * D_ + t];
        g_xa[(size_t)n * KA + t] = __float2half(x);
        return;
    }
    if (blk < PREP_X_BLKS + PREP_W_BLKS) {
        // ---- w transpose to [u][d] fp16 ----
        int idx = blk - PREP_X_BLKS;
        int z = idx >> 6;             // /64
        int rem = idx & 63;
        int u0 = (rem & 7) * 32, d0 = (rem >> 3) * 32;
        const float* W;
        if (z < L_)          W = Vin  + (size_t)z * D_ * U_;
        else if (z < 2 * L_) W = Vout + (size_t)(z - L_) * D_ * U_;
        else                 W = Ws;
        __shared__ float tile[32][33];
        int tx = t & 31, ty = t >> 5;     // 32 x 8
        #pragma unroll
        for (int j = 0; j < 32; j += 8)
            tile[ty + j][tx] = W[(size_t)(d0 + ty + j) * U_ + u0 + tx];
        __syncthreads();
        __half* base = g_wb + (size_t)z * U_ * KB;
        #pragma unroll
        for (int j = 0; j < 32; j += 8) {
            int u = u0 + ty + j, d = d0 + tx;
            base[(size_t)u * KB + d] = __float2half(tile[tx][ty + j]);
        }
        return;
    }
    if (blk < PREP_X_BLKS + PREP_W_BLKS + PREP_E_BLKS) {
        // ---- edge decode ----
        __shared__ int s64;
        if (t == 0) s64 = detect_is64((const int*)arc_in);
        __syncthreads();
        int e = (blk - PREP_X_BLKS - PREP_W_BLKS) * 256 + t;
        int bi, si, li, bo, so, lo;
        if (s64) {
            const long long* ai = (const long long*)arc_in;
            const long long* ao = (const long long*)arc_out;
            bi = (int)ai[e];  si = (int)ai[E_ + e];  li = (int)((const long long*)lab_in)[e];
            bo = (int)ao[e];  so = (int)ao[E_ + e];  lo = (int)((const long long*)lab_out)[e];
        } else {
            const int* ai = (const int*)arc_in;
            const int* ao = (const int*)arc_out;
            bi = ai[e];  si = ai[E_ + e];  li = ((const int*)lab_in)[e];
            bo = ao[e];  so = ao[E_ + e];  lo = ((const int*)lab_out)[e];
        }
        g_ein[e]  = bi * S_ + si;  g_lin[e]  = li;
        g_eout[e] = bo * S_ + so;  g_lout[e] = lo;
        return;
    }
    // ---- gates (fp32, exact) ----
    {
        int base = blk - PREP_X_BLKS - PREP_W_BLKS - PREP_E_BLKS;
        int warp = base * 8 + (t >> 5);
        int lane = t & 31;
        int s = warp & (S_ - 1);
        int b = warp >> 8;
        const float* xr = src + (size_t)s * B_ * D_ + (size_t)b * D_;
        float a = 0.f, bb = 0.f, c = 0.f;
        #pragma unroll
        for (int d = lane; d < D_; d += 32) {
            float xv = xr[d];
            a  += xv * vgin[d];
            bb += xv * vgout[d];
            c  += xv * wgloop[d];
        }
        #pragma unroll
        for (int off = 16; off; off >>= 1) {
            a  += __shfl_xor_sync(0xffffffffu, a, off);
            bb += __shfl_xor_sync(0xffffffffu, bb, off);
            c  += __shfl_xor_sync(0xffffffffu, c, off);
        }
        if (lane == 0) { g_gin[warp] = a; g_gout[warp] = bb; g_gloop[warp] = c; }
    }
}

// ---------------------------------------------------------------------------
// mma.sync fp16 GEMM (R12 configuration): C[mat] = x16 @ w16[mat]^T, fp16 out
// ---------------------------------------------------------------------------
__device__ __forceinline__ void load_stage(uint32_t sbase, int buf, int kt,
                                           const __half* wrow0, int m0, int t) {
    uint32_t ab = sbase + buf * STAGE;
    uint32_t bb = ab + MTILE * 128;
    #pragma unroll
    for (int r = 0; r < 4; r++) {
        int i = r * 256 + t;                  // 1024 16B segments (A)
        int row = i >> 3, seg = i & 7;
        const char* src = (const char*)g_xa +
            (((size_t)(m0 + row) * KA + (size_t)kt * BK) << 1) + seg * 16;
        cp_async16(ab + swz128(row * 128 + seg * 16), src);
    }
    #pragma unroll
    for (int r = 0; r < 4; r++) {
        int i = r * 256 + t;                  // 1024 16B segments (B)
        int row = i >> 3, seg = i & 7;
        const char* src = (const char*)wrow0 +
            (((size_t)row * KB + (size_t)kt * BK) << 1) + seg * 16;
        cp_async16(bb + swz128(row * 128 + seg * 16), src);
    }
}

__global__ void __launch_bounds__(256, 2) gemm_mma_kernel() {
    extern __shared__ char smem[];
    uint32_t sbase = smem_u32(smem);
    const int t = threadIdx.x, wid = t >> 5, lane = t & 31;
    const int wm = wid & 1, wn = wid >> 1;            // 2m x 4n warp grid
    const int mat = blockIdx.z;
    const int m0 = blockIdx.x * MTILE, n0 = blockIdx.y * NTILE;
    const __half* wrow0 = g_wb + (size_t)mat * U_ * KB + (size_t)n0 * KB;

    float acc[4][4][4];
    #pragma unroll
    for (int i = 0; i < 4; i++)
        #pragma unroll
        for (int j = 0; j < 4; j++)
            #pragma unroll
            for (int q = 0; q < 4; q++) acc[i][j][q] = 0.f;

    load_stage(sbase, 0, 0, wrow0, m0, t);
    CP_COMMIT();

    const int a_row = wm * 64 + (lane & 15);
    const int a_cb  = (lane >> 4) * 16;
    const int b_row = wn * 32 + (lane & 7);
    const int b_cb  = ((lane >> 3) & 1) * 16;

    for (int kt = 0; kt < NCHUNK; kt++) {
        const int buf = kt & 1;
        if (kt + 1 < NCHUNK) {
            load_stage(sbase, buf ^ 1, kt + 1, wrow0, m0, t);
            CP_COMMIT();
            asm volatile("cp.async.wait_group 1;" ::: "memory");
        } else {
            asm volatile("cp.async.wait_group 0;" ::: "memory");
        }
        __syncthreads();

        uint32_t ab = sbase + buf * STAGE;
        uint32_t bb = ab + MTILE * 128;
        #pragma unroll
        for (int ks = 0; ks < 4; ks++) {
            const int kb = ks * 32;
            uint32_t a_frag[4][4], b_frag[4][2];
            #pragma unroll
            for (int mi = 0; mi < 4; mi++)
                ldmatrix_x4(a_frag[mi],
                    ab + swz128((a_row + mi * 16) * 128 + kb + a_cb));
            #pragma unroll
            for (int ni = 0; ni < 4; ni++)
                ldmatrix_x2(b_frag[ni],
                    bb + swz128((b_row + ni * 8) * 128 + kb + b_cb));
            #pragma unroll
            for (int mi = 0; mi < 4; mi++)
                #pragma unroll
                for (int ni = 0; ni < 4; ni++)
                    mma_f16(acc[mi][ni], a_frag[mi], b_frag[ni]);
        }
        __syncthreads();
    }

    __half* C;
    if (mat < L_)            C = g_all_in  + (size_t)mat * N_ * U_;
    else if (mat < 2 * L_)   C = g_all_out + (size_t)(mat - L_) * N_ * U_;
    else                     C = g_same;

    const int r0 = m0 + wm * 64 + (lane >> 2);
    const int c0 = n0 + wn * 32 + (lane & 3) * 2;
    #pragma unroll
    for (int mi = 0; mi < 4; mi++) {
        #pragma unroll
        for (int ni = 0; ni < 4; ni++) {
            __half* p0 = C + (size_t)(r0 + mi * 16) * U_ + c0 + ni * 8;
            __half* p1 = p0 + 8 * U_;
            *(__half2*)p0 = __floats2half2_rn(acc[mi][ni][0], acc[mi][ni][1]);
            *(__half2*)p1 = __floats2half2_rn(acc[mi][ni][2], acc[mi][ni][3]);
        }
    }
}

// ---------------------------------------------------------------------------
// Gather + sigmoid-gated reduce + relu + sent_mask + transpose to [S,B,U]
// ---------------------------------------------------------------------------
__device__ __forceinline__ float sigmoidf_(float g) { return 1.f / (1.f + expf(-g)); }

__global__ void gather_kernel(const float* __restrict__ b_in,
                              const float* __restrict__ bg_in,
                              const float* __restrict__ b_out,
                              const float* __restrict__ bg_out,
                              const float* __restrict__ mask_in,
                              const float* __restrict__ mask_out,
                              const float* __restrict__ mask_loop,
                              const float* __restrict__ sent_mask,
                              float* __restrict__ out) {
    const int n = blockIdx.x;
    const int t = threadIdx.x;
    const int s = n & (S_ - 1);
    const int b = n >> 8;

    __shared__ float sp[33];
    __shared__ int   sidx[33];
    __shared__ int   sl[33];

    if (t < 33) {
        float p; int idx = 0, l = 0;
        if (t < 16) {
            int e = n * DEG_ + t;
            idx = g_ein[e]; l = g_lin[e];
            p = sigmoidf_(g_gin[idx] + bg_in[l]) * mask_in[(size_t)n * DEG_ + t];
        } else if (t < 32) {
            int k = t - 16;
            int e = n * DEG_ + k;
            idx = g_eout[e]; l = g_lout[e];
            p = sigmoidf_(g_gout[idx] + bg_out[l]) * mask_out[(size_t)n * DEG_ + k];
        } else {
            p = sigmoidf_(g_gloop[n]) * mask_loop[n];
        }
        sp[t] = p; sidx[t] = idx; sl[t] = l;
    }
    __syncthreads();

    const float sent = sent_mask[(size_t)s * B_ + b];
    float acc = sp[32] * __half2float(g_same[(size_t)n * U_ + t]);
    #pragma unroll
    for (int k = 0; k < 16; k++) {
        int l = sl[k];
        acc += sp[k] * (__half2float(g_all_in[((size_t)l * N_ + sidx[k]) * U_ + t])
                        + b_in[l * U_ + t]);
    }
    #pragma unroll
    for (int k = 16; k < 32; k++) {
        int l = sl[k];
        acc += sp[k] * (__half2float(g_all_out[((size_t)l * N_ + sidx[k]) * U_ + t])
                        + b_out[l * U_ + t]);
    }
    acc = fmaxf(acc, 0.f) * sent;
    out[(size_t)s * B_ * U_ + (size_t)b * U_ + t] = acc;
}

// ---------------------------------------------------------------------------
// Launch
// ---------------------------------------------------------------------------
extern "C" void kernel_launch(void* const* d_in, const int* in_sizes, int n_in,
                              void* d_out, int out_size) {
    const float* src        = (const float*)d_in[0];
    const float* V_in       = (const float*)d_in[1];
    const float* b_in       = (const float*)d_in[2];
    const float* V_in_gate  = (const float*)d_in[3];
    const float* b_in_gate  = (const float*)d_in[4];
    const float* V_out      = (const float*)d_in[5];
    const float* b_out      = (const float*)d_in[6];
    const float* V_out_gate = (const float*)d_in[7];
    const float* b_out_gate = (const float*)d_in[8];
    const float* W_self     = (const float*)d_in[9];
    const float* W_self_g   = (const float*)d_in[10];
    const void*  arc_in     = d_in[11];
    const void*  arc_out    = d_in[12];
    const void*  lab_in     = d_in[13];
    const void*  lab_out    = d_in[14];
    const float* mask_in    = (const float*)d_in[15];
    const float* mask_out   = (const float*)d_in[16];
    const float* mask_loop  = (const float*)d_in[17];
    const float* sent_mask  = (const float*)d_in[18];
    float* out = (float*)d_out;

    cudaFuncSetAttribute(gemm_mma_kernel,
                         cudaFuncAttributeMaxDynamicSharedMemorySize, SMEM_TOTAL);

    prep_fused_kernel<<<PREP_TOTAL, 256>>>(src, V_in, V_out, W_self,
                                           arc_in, lab_in, arc_out, lab_out,
                                           V_in_gate, V_out_gate, W_self_g);

    gemm_mma_kernel<<<dim3(N_ / MTILE, U_ / NTILE, NMAT), 256, SMEM_TOTAL>>>();

    gather_kernel<<<N_, U_>>>(b_in, b_in_gate, b_out, b_out_gate,
                              mask_in, mask_out, mask_loop, sent_mask, out);
}

// round 17
// speedup vs baseline: 1.2381x; 1.1484x over previous
#include <cuda_runtime.h>
#include <cuda_bf16.h>
#include <cuda_fp16.h>
#include <cstdint>

// Problem constants
#define B_    32
#define S_    256
#define D_    256
#define U_    256
#define L_    16
#define DEG_  16
#define N_    (B_ * S_)        // 8192
#define E_    (N_ * DEG_)      // 131072
#define KA    256              // fp16 x
#define KB    256              // fp16 w^T
#define NMAT  33               // 16 in + 16 out + 1 self

// GEMM tiling: CTA 128x128, 8 warps (2m x 4n), warp tile 64x32, occ 2
// (A,B) chunk pairs double-buffered -- frozen R12 configuration.
#define MTILE   128
#define NTILE   128
#define BK      64                         // fp16 per K-chunk (128B rows)
#define NCHUNK  (KA / BK)                  // 4
#define STAGE   (MTILE * 128 + NTILE * 128)    // 16KB A + 16KB B = 32768
#define SMEM_TOTAL (2 * STAGE)             // 65536

// Fused prep block ranges
#define PREP_X_BLKS   (N_ * D_ / 1024)    // 2048 (4 elems/thread)
#define PREP_W_BLKS   (64 * NMAT)         // 2112
#define PREP_E_BLKS   (E_ / 256)          // 512
#define PREP_G_BLKS   (N_ / 8)            // 1024
#define PREP_TOTAL (PREP_X_BLKS + PREP_W_BLKS + PREP_E_BLKS + PREP_G_BLKS)

// ---------------------------------------------------------------------------
// Scratch (device globals: allocation-free rule)
// ---------------------------------------------------------------------------
__device__ __align__(16) __half g_xa[(size_t)N_ * KA];            // [N,256] fp16 x
__device__ __align__(16) __half g_wb[(size_t)NMAT * U_ * KB];     // [33][u][256] fp16 w^T
__device__ __align__(16) __half g_all_in [(size_t)L_ * N_ * U_];  // fp16 potentials
__device__ __align__(16) __half g_all_out[(size_t)L_ * N_ * U_];
__device__ __align__(16) __half g_same[(size_t)N_ * U_];
__device__ float g_gin[N_], g_gout[N_], g_gloop[N_];
__device__ int   g_ein[E_], g_lin[E_], g_eout[E_], g_lout[E_];

// ---------------------------------------------------------------------------
// PTX helpers (sm_80+-portable only)
// ---------------------------------------------------------------------------
__device__ __forceinline__ uint32_t smem_u32(const void* p) {
    uint32_t a;
    asm("{ .reg .u64 t; cvta.to.shared.u64 t, %1; cvt.u32.u64 %0, t; }" : "=r"(a) : "l"(p));
    return a;
}
__device__ __forceinline__ void cp_async16(uint32_t dst, const void* src) {
    asm volatile("cp.async.cg.shared.global [%0], [%1], 16;" :: "r"(dst), "l"(src) : "memory");
}
#define CP_COMMIT() asm volatile("cp.async.commit_group;" ::: "memory")

__device__ __forceinline__ uint32_t swz128(uint32_t off) {
    return off ^ ((off >> 3) & 0x70);
}
__device__ __forceinline__ void ldmatrix_x4(uint32_t* r, uint32_t addr) {
    asm volatile("ldmatrix.sync.aligned.m8n8.x4.shared.b16 {%0,%1,%2,%3}, [%4];"
                 : "=r"(r[0]), "=r"(r[1]), "=r"(r[2]), "=r"(r[3]) : "r"(addr));
}
__device__ __forceinline__ void ldmatrix_x2(uint32_t* r, uint32_t addr) {
    asm volatile("ldmatrix.sync.aligned.m8n8.x2.shared.b16 {%0,%1}, [%2];"
                 : "=r"(r[0]), "=r"(r[1]) : "r"(addr));
}
__device__ __forceinline__ void mma_f16(float* c, const uint32_t* a, const uint32_t* b) {
    asm volatile(
        "mma.sync.aligned.m16n8k16.row.col.f32.f16.f16.f32 "
        "{%0,%1,%2,%3}, {%4,%5,%6,%7}, {%8,%9}, {%0,%1,%2,%3};"
        : "+f"(c[0]), "+f"(c[1]), "+f"(c[2]), "+f"(c[3])
        : "r"(a[0]), "r"(a[1]), "r"(a[2]), "r"(a[3]), "r"(b[0]), "r"(b[1]));
}

// ---------------------------------------------------------------------------
// Fused prep: x-convert | w-transpose | edge-decode | gates, by block range
// ---------------------------------------------------------------------------
__device__ __forceinline__ int detect_is64(const int* p) {
    int z = 1;
    #pragma unroll
    for (int i = 1; i < 128; i += 2) z &= (p[i] == 0);
    return z;
}

__global__ void prep_fused_kernel(const float* __restrict__ src,
                                  const float* __restrict__ Vin,
                                  const float* __restrict__ Vout,
                                  const float* __restrict__ Ws,
                                  const void* __restrict__ arc_in,
                                  const void* __restrict__ lab_in,
                                  const void* __restrict__ arc_out,
                                  const void* __restrict__ lab_out,
                                  const float* __restrict__ vgin,
                                  const float* __restrict__ vgout,
                                  const float* __restrict__ wgloop) {
    const int blk = blockIdx.x;
    const int t = threadIdx.x;

    if (blk < PREP_X_BLKS) {
        // ---- x fp16 convert, 4 elems/thread (float4 -> 2x half2) ----
        int g = blk * 256 + t;          // float4-group index, row has 64 groups
        int n = g >> 6;
        int quad = g & 63;
        int s = n & (S_ - 1);
        int b = n >> 8;
        float4 v = ((const float4*)src)[((size_t)s * B_ + b) * 64 + quad];
        uint2 pk;
        __half2 h0 = __floats2half2_rn(v.x, v.y);
        __half2 h1 = __floats2half2_rn(v.z, v.w);
        pk.x = *(uint32_t*)&h0;
        pk.y = *(uint32_t*)&h1;
        ((uint2*)g_xa)[(size_t)n * 64 + quad] = pk;
        return;
    }
    if (blk < PREP_X_BLKS + PREP_W_BLKS) {
        // ---- w transpose to [u][d] fp16 ----
        int idx = blk - PREP_X_BLKS;
        int z = idx >> 6;
        int rem = idx & 63;
        int u0 = (rem & 7) * 32, d0 = (rem >> 3) * 32;
        const float* W;
        if (z < L_)          W = Vin  + (size_t)z * D_ * U_;
        else if (z < 2 * L_) W = Vout + (size_t)(z - L_) * D_ * U_;
        else                 W = Ws;
        __shared__ float tile[32][33];
        int tx = t & 31, ty = t >> 5;     // 32 x 8
        #pragma unroll
        for (int j = 0; j < 32; j += 8)
            tile[ty + j][tx] = W[(size_t)(d0 + ty + j) * U_ + u0 + tx];
        __syncthreads();
        __half* base = g_wb + (size_t)z * U_ * KB;
        #pragma unroll
        for (int j = 0; j < 32; j += 8) {
            int u = u0 + ty + j, d = d0 + tx;
            base[(size_t)u * KB + d] = __float2half(tile[tx][ty + j]);
        }
        return;
    }
    if (blk < PREP_X_BLKS + PREP_W_BLKS + PREP_E_BLKS) {
        // ---- edge decode ----
        __shared__ int s64;
        if (t == 0) s64 = detect_is64((const int*)arc_in);
        __syncthreads();
        int e = (blk - PREP_X_BLKS - PREP_W_BLKS) * 256 + t;
        int bi, si, li, bo, so, lo;
        if (s64) {
            const long long* ai = (const long long*)arc_in;
            const long long* ao = (const long long*)arc_out;
            bi = (int)ai[e];  si = (int)ai[E_ + e];  li = (int)((const long long*)lab_in)[e];
            bo = (int)ao[e];  so = (int)ao[E_ + e];  lo = (int)((const long long*)lab_out)[e];
        } else {
            const int* ai = (const int*)arc_in;
            const int* ao = (const int*)arc_out;
            bi = ai[e];  si = ai[E_ + e];  li = ((const int*)lab_in)[e];
            bo = ao[e];  so = ao[E_ + e];  lo = ((const int*)lab_out)[e];
        }
        g_ein[e]  = bi * S_ + si;  g_lin[e]  = li;
        g_eout[e] = bo * S_ + so;  g_lout[e] = lo;
        return;
    }
    // ---- gates (fp32, exact) ----
    {
        int base = blk - PREP_X_BLKS - PREP_W_BLKS - PREP_E_BLKS;
        int warp = base * 8 + (t >> 5);
        int lane = t & 31;
        int s = warp & (S_ - 1);
        int b = warp >> 8;
        const float* xr = src + (size_t)s * B_ * D_ + (size_t)b * D_;
        float a = 0.f, bb = 0.f, c = 0.f;
        #pragma unroll
        for (int d = lane; d < D_; d += 32) {
            float xv = xr[d];
            a  += xv * vgin[d];
            bb += xv * vgout[d];
            c  += xv * wgloop[d];
        }
        #pragma unroll
        for (int off = 16; off; off >>= 1) {
            a  += __shfl_xor_sync(0xffffffffu, a, off);
            bb += __shfl_xor_sync(0xffffffffu, bb, off);
            c  += __shfl_xor_sync(0xffffffffu, c, off);
        }
        if (lane == 0) { g_gin[warp] = a; g_gout[warp] = bb; g_gloop[warp] = c; }
    }
}

// ---------------------------------------------------------------------------
// mma.sync fp16 GEMM (frozen R12 configuration)
// ---------------------------------------------------------------------------
__device__ __forceinline__ void load_stage(uint32_t sbase, int buf, int kt,
                                           const __half* wrow0, int m0, int t) {
    uint32_t ab = sbase + buf * STAGE;
    uint32_t bb = ab + MTILE * 128;
    #pragma unroll
    for (int r = 0; r < 4; r++) {
        int i = r * 256 + t;
        int row = i >> 3, seg = i & 7;
        const char* src = (const char*)g_xa +
            (((size_t)(m0 + row) * KA + (size_t)kt * BK) << 1) + seg * 16;
        cp_async16(ab + swz128(row * 128 + seg * 16), src);
    }
    #pragma unroll
    for (int r = 0; r < 4; r++) {
        int i = r * 256 + t;
        int row = i >> 3, seg = i & 7;
        const char* src = (const char*)wrow0 +
            (((size_t)row * KB + (size_t)kt * BK) << 1) + seg * 16;
        cp_async16(bb + swz128(row * 128 + seg * 16), src);
    }
}

__global__ void __launch_bounds__(256, 2) gemm_mma_kernel() {
    extern __shared__ char smem[];
    uint32_t sbase = smem_u32(smem);
    const int t = threadIdx.x, wid = t >> 5, lane = t & 31;
    const int wm = wid & 1, wn = wid >> 1;
    const int mat = blockIdx.z;
    const int m0 = blockIdx.x * MTILE, n0 = blockIdx.y * NTILE;
    const __half* wrow0 = g_wb + (size_t)mat * U_ * KB + (size_t)n0 * KB;

    float acc[4][4][4];
    #pragma unroll
    for (int i = 0; i < 4; i++)
        #pragma unroll
        for (int j = 0; j < 4; j++)
            #pragma unroll
            for (int q = 0; q < 4; q++) acc[i][j][q] = 0.f;

    load_stage(sbase, 0, 0, wrow0, m0, t);
    CP_COMMIT();

    const int a_row = wm * 64 + (lane & 15);
    const int a_cb  = (lane >> 4) * 16;
    const int b_row = wn * 32 + (lane & 7);
    const int b_cb  = ((lane >> 3) & 1) * 16;

    for (int kt = 0; kt < NCHUNK; kt++) {
        const int buf = kt & 1;
        if (kt + 1 < NCHUNK) {
            load_stage(sbase, buf ^ 1, kt + 1, wrow0, m0, t);
            CP_COMMIT();
            asm volatile("cp.async.wait_group 1;" ::: "memory");
        } else {
            asm volatile("cp.async.wait_group 0;" ::: "memory");
        }
        __syncthreads();

        uint32_t ab = sbase + buf * STAGE;
        uint32_t bb = ab + MTILE * 128;
        #pragma unroll
        for (int ks = 0; ks < 4; ks++) {
            const int kb = ks * 32;
            uint32_t a_frag[4][4], b_frag[4][2];
            #pragma unroll
            for (int mi = 0; mi < 4; mi++)
                ldmatrix_x4(a_frag[mi],
                    ab + swz128((a_row + mi * 16) * 128 + kb + a_cb));
            #pragma unroll
            for (int ni = 0; ni < 4; ni++)
                ldmatrix_x2(b_frag[ni],
                    bb + swz128((b_row + ni * 8) * 128 + kb + b_cb));
            #pragma unroll
            for (int mi = 0; mi < 4; mi++)
                #pragma unroll
                for (int ni = 0; ni < 4; ni++)
                    mma_f16(acc[mi][ni], a_frag[mi], b_frag[ni]);
        }
        __syncthreads();
    }

    __half* C;
    if (mat < L_)            C = g_all_in  + (size_t)mat * N_ * U_;
    else if (mat < 2 * L_)   C = g_all_out + (size_t)(mat - L_) * N_ * U_;
    else                     C = g_same;

    const int r0 = m0 + wm * 64 + (lane >> 2);
    const int c0 = n0 + wn * 32 + (lane & 3) * 2;
    #pragma unroll
    for (int mi = 0; mi < 4; mi++) {
        #pragma unroll
        for (int ni = 0; ni < 4; ni++) {
            __half* p0 = C + (size_t)(r0 + mi * 16) * U_ + c0 + ni * 8;
            __half* p1 = p0 + 8 * U_;
            *(__half2*)p0 = __floats2half2_rn(acc[mi][ni][0], acc[mi][ni][1]);
            *(__half2*)p1 = __floats2half2_rn(acc[mi][ni][2], acc[mi][ni][3]);
        }
    }
}

// ---------------------------------------------------------------------------
// Gather: 2 nodes/block, half2 per thread. Same per-element math order.
// ---------------------------------------------------------------------------
__device__ __forceinline__ float sigmoidf_(float g) { return 1.f / (1.f + expf(-g)); }

__global__ void gather_kernel(const float* __restrict__ b_in,
                              const float* __restrict__ bg_in,
                              const float* __restrict__ b_out,
                              const float* __restrict__ bg_out,
                              const float* __restrict__ mask_in,
                              const float* __restrict__ mask_out,
                              const float* __restrict__ mask_loop,
                              const float* __restrict__ sent_mask,
                              float* __restrict__ out) {
    const int blk = blockIdx.x;            // 0..4095
    const int t = threadIdx.x;             // 0..255
    const int hf = t >> 7;                 // node select within block
    const int n = blk * 2 + hf;
    const int uh = t & 127;                // half2 index: u = 2*uh
    const int s = n & (S_ - 1);
    const int b = n >> 8;

    __shared__ float sp[2][33];
    __shared__ int   sidx[2][33];
    __shared__ int   sl[2][33];

    if (uh < 33) {
        float p; int idx = 0, l = 0;
        if (uh < 16) {
            int e = n * DEG_ + uh;
            idx = g_ein[e]; l = g_lin[e];
            p = sigmoidf_(g_gin[idx] + bg_in[l]) * mask_in[(size_t)n * DEG_ + uh];
        } else if (uh < 32) {
            int k = uh - 16;
            int e = n * DEG_ + k;
            idx = g_eout[e]; l = g_lout[e];
            p = sigmoidf_(g_gout[idx] + bg_out[l]) * mask_out[(size_t)n * DEG_ + k];
        } else {
            p = sigmoidf_(g_gloop[n]) * mask_loop[n];
        }
        sp[hf][uh] = p; sidx[hf][uh] = idx; sl[hf][uh] = l;
    }
    __syncthreads();

    const float sent = sent_mask[(size_t)s * B_ + b];
    const float pl = sp[hf][32];
    __half2 sm = ((const __half2*)(g_same + (size_t)n * U_))[uh];
    float accx = pl * __low2float(sm);
    float accy = pl * __high2float(sm);
    #pragma unroll
    for (int k = 0; k < 16; k++) {
        int l = sl[hf][k];
        float p = sp[hf][k];
        __half2 h = ((const __half2*)(g_all_in + ((size_t)l * N_ + sidx[hf][k]) * U_))[uh];
        float2 bi = *(const float2*)(b_in + l * U_ + 2 * uh);
        accx += p * (__low2float(h)  + bi.x);
        accy += p * (__high2float(h) + bi.y);
    }
    #pragma unroll
    for (int k = 16; k < 32; k++) {
        int l = sl[hf][k];
        float p = sp[hf][k];
        __half2 h = ((const __half2*)(g_all_out + ((size_t)l * N_ + sidx[hf][k]) * U_))[uh];
        float2 bo = *(const float2*)(b_out + l * U_ + 2 * uh);
        accx += p * (__low2float(h)  + bo.x);
        accy += p * (__high2float(h) + bo.y);
    }
    float2 r;
    r.x = fmaxf(accx, 0.f) * sent;
    r.y = fmaxf(accy, 0.f) * sent;
    ((float2*)(out + (size_t)s * B_ * U_ + (size_t)b * U_))[uh] = r;
}

// ---------------------------------------------------------------------------
// Launch
// ---------------------------------------------------------------------------
extern "C" void kernel_launch(void* const* d_in, const int* in_sizes, int n_in,
                              void* d_out, int out_size) {
    const float* src        = (const float*)d_in[0];
    const float* V_in       = (const float*)d_in[1];
    const float* b_in       = (const float*)d_in[2];
    const float* V_in_gate  = (const float*)d_in[3];
    const float* b_in_gate  = (const float*)d_in[4];
    const float* V_out      = (const float*)d_in[5];
    const float* b_out      = (const float*)d_in[6];
    const float* V_out_gate = (const float*)d_in[7];
    const float* b_out_gate = (const float*)d_in[8];
    const float* W_self     = (const float*)d_in[9];
    const float* W_self_g   = (const float*)d_in[10];
    const void*  arc_in     = d_in[11];
    const void*  arc_out    = d_in[12];
    const void*  lab_in     = d_in[13];
    const void*  lab_out    = d_in[14];
    const float* mask_in    = (const float*)d_in[15];
    const float* mask_out   = (const float*)d_in[16];
    const float* mask_loop  = (const float*)d_in[17];
    const float* sent_mask  = (const float*)d_in[18];
    float* out = (float*)d_out;

    cudaFuncSetAttribute(gemm_mma_kernel,
                         cudaFuncAttributeMaxDynamicSharedMemorySize, SMEM_TOTAL);

    prep_fused_kernel<<<PREP_TOTAL, 256>>>(src, V_in, V_out, W_self,
                                           arc_in, lab_in, arc_out, lab_out,
                                           V_in_gate, V_out_gate, W_self_g);

    gemm_mma_kernel<<<dim3(N_ / MTILE, U_ / NTILE, NMAT), 256, SMEM_TOTAL>>>();

    gather_kernel<<<N_ / 2, 256>>>(b_in, b_in_gate, b_out, b_out_gate,
                                   mask_in, mask_out, mask_loop, sent_mask, out);
}